// round 2
// baseline (speedup 1.0000x reference)
#include <cuda_runtime.h>
#include <math.h>

#define NMAX 100000
#define EMAX 1000000
#define HDIM 64
#define NGRAPH 128
#define NCLS 5

// ---------------- scratch (device globals; no allocs allowed) ----------------
__device__ int   g_deg[NMAX];
__device__ int   g_cursor[NMAX];
__device__ int   g_off[NMAX];
__device__ int   g_bsum[256];
__device__ float g_dinv[NMAX];
__device__ int   g_csrc[EMAX];
__device__ float g_cnorm[EMAX];
__device__ __align__(16) float g_ax[NMAX * 2];
__device__ __align__(16) float g_h[NMAX * HDIM];
__device__ __align__(16) float g_a[NMAX * HDIM];
__device__ int   g_gstart[NGRAPH + 1];
__device__ __align__(16) float g_pooled[NGRAPH * HDIM];

// buffer selector — device globals must NEVER be passed from host code
// (host-side names are shadow symbols; on GB300 ATS they silently alias host RAM)
__device__ __forceinline__ float* selbuf(int b) { return b == 0 ? g_h : g_a; }

// ---------------- pipeline kernels ----------------

__global__ void k_zero(int n) {
    int i = blockIdx.x * blockDim.x + threadIdx.x;
    if (i < n) { g_deg[i] = 0; g_cursor[i] = 0; }
}

__global__ void k_count(const int* __restrict__ dst, int e) {
    int i = blockIdx.x * blockDim.x + threadIdx.x;
    if (i < e) atomicAdd(&g_deg[dst[i]], 1);
}

__global__ void k_dinv(int n) {
    int i = blockIdx.x * blockDim.x + threadIdx.x;
    if (i < n) g_dinv[i] = rsqrtf((float)(g_deg[i] + 1));  // +1 self-loop
}

// exclusive scan of g_deg -> g_off, phase A: per-block (1024) scan + block sums
__global__ void k_scanA(int n) {
    int i = blockIdx.x * 1024 + threadIdx.x;
    int v = (i < n) ? g_deg[i] : 0;
    int lane = threadIdx.x & 31, wid = threadIdx.x >> 5;
    int x = v;
    #pragma unroll
    for (int o = 1; o < 32; o <<= 1) {
        int y = __shfl_up_sync(0xffffffffu, x, o);
        if (lane >= o) x += y;
    }
    __shared__ int ws[32];
    if (lane == 31) ws[wid] = x;
    __syncthreads();
    if (wid == 0) {
        int s = ws[lane];
        #pragma unroll
        for (int o = 1; o < 32; o <<= 1) {
            int y = __shfl_up_sync(0xffffffffu, s, o);
            if (lane >= o) s += y;
        }
        ws[lane] = s;
    }
    __syncthreads();
    int warpoff = (wid == 0) ? 0 : ws[wid - 1];
    if (i < n) g_off[i] = warpoff + x - v;          // exclusive within block
    if (threadIdx.x == 0) g_bsum[blockIdx.x] = ws[31];
}

__global__ void k_scanB(int nb) {
    if (threadIdx.x == 0) {
        int acc = 0;
        for (int b = 0; b < nb; b++) { int t = g_bsum[b]; g_bsum[b] = acc; acc += t; }
    }
}

__global__ void k_scanC(int n) {
    int i = blockIdx.x * blockDim.x + threadIdx.x;
    if (i < n) g_off[i] += g_bsum[i >> 10];
}

__global__ void k_scatter(const int* __restrict__ ei, int e) {
    int i = blockIdx.x * blockDim.x + threadIdx.x;
    if (i >= e) return;
    int s = ei[i];
    int d = ei[e + i];
    int p = g_off[d] + atomicAdd(&g_cursor[d], 1);
    g_csrc[p] = s;
    g_cnorm[p] = g_dinv[s] * g_dinv[d];
}

// aggregate 2-wide raw features (layer-1 pre-aggregation; linear commutes)
__global__ void k_agg2(const float* __restrict__ x, int n) {
    int v = blockIdx.x * blockDim.x + threadIdx.x;
    if (v >= n) return;
    const float2* x2 = (const float2*)x;
    float ax = 0.f, ay = 0.f;
    int st = g_off[v], c = g_deg[v];
    for (int j = 0; j < c; j++) {
        int s = __ldg(&g_csrc[st + j]);
        float nm = __ldg(&g_cnorm[st + j]);
        float2 xv = x2[s];
        ax = fmaf(nm, xv.x, ax);
        ay = fmaf(nm, xv.y, ay);
    }
    float dv = g_dinv[v];
    float nm = dv * dv;
    float2 xv = x2[v];
    ax = fmaf(nm, xv.x, ax);
    ay = fmaf(nm, xv.y, ay);
    g_ax[2 * v] = ax;
    g_ax[2 * v + 1] = ay;
}

// h1 = relu(agg_x @ W1 + b1)   (W1: [2,64] row-major)
__global__ void k_lin1(const float* __restrict__ W1, const float* __restrict__ b1, int n) {
    int idx = blockIdx.x * blockDim.x + threadIdx.x;
    if (idx >= n * HDIM) return;
    int v = idx >> 6, c = idx & 63;
    float o = fmaf(g_ax[2 * v], __ldg(&W1[c]),
              fmaf(g_ax[2 * v + 1], __ldg(&W1[HDIM + c]), __ldg(&b1[c])));
    g_h[idx] = fmaxf(o, 0.f);
}

// 64-wide aggregation: one warp per node, lane covers cols {lane, lane+32}
__global__ void k_agg64(int ib, int ob, int n) {
    const float* in  = selbuf(ib);
    float*       out = selbuf(ob);
    int w = (blockIdx.x * blockDim.x + threadIdx.x) >> 5;
    int lane = threadIdx.x & 31;
    if (w >= n) return;
    int st = g_off[w], c = g_deg[w];
    float a0 = 0.f, a1 = 0.f;
    int j = 0;
    for (; j + 1 < c; j += 2) {
        int   s0 = __ldg(&g_csrc[st + j]);
        int   s1 = __ldg(&g_csrc[st + j + 1]);
        float n0 = __ldg(&g_cnorm[st + j]);
        float n1 = __ldg(&g_cnorm[st + j + 1]);
        const float* r0 = in + (long)s0 * HDIM;
        const float* r1 = in + (long)s1 * HDIM;
        float v00 = r0[lane], v01 = r0[lane + 32];
        float v10 = r1[lane], v11 = r1[lane + 32];
        a0 = fmaf(n0, v00, a0); a1 = fmaf(n0, v01, a1);
        a0 = fmaf(n1, v10, a0); a1 = fmaf(n1, v11, a1);
    }
    if (j < c) {
        int   s0 = __ldg(&g_csrc[st + j]);
        float n0 = __ldg(&g_cnorm[st + j]);
        const float* r0 = in + (long)s0 * HDIM;
        a0 = fmaf(n0, r0[lane], a0);
        a1 = fmaf(n0, r0[lane + 32], a1);
    }
    float dv = g_dinv[w];
    float nm = dv * dv;
    a0 = fmaf(nm, in[(long)w * HDIM + lane], a0);
    a1 = fmaf(nm, in[(long)w * HDIM + lane + 32], a1);
    out[(long)w * HDIM + lane] = a0;
    out[(long)w * HDIM + lane + 32] = a1;
}

// out = (relu?)(in @ W + b), in/out [n,64], W [64,64]. blockDim=128.
// 8 nodes per iter; thread computes 4 cols via float4.
__global__ void k_gemm(int ib, int ob, const float* __restrict__ W,
                       const float* __restrict__ b, int n, int relu) {
    const float4* in4  = (const float4*)selbuf(ib);
    float4*       out4 = (float4*)selbuf(ob);
    __shared__ float4 sW[64 * 16];
    __shared__ float4 sB4[16];
    __shared__ float  sH[8 * 64];
    int t = threadIdx.x;
    const float4* W4 = (const float4*)W;
    for (int i = t; i < 1024; i += 128) sW[i] = W4[i];
    if (t < 16) sB4[t] = ((const float4*)b)[t];
    __syncthreads();

    int ngroups = (n + 7) / 8;
    int nl = t >> 4, g = t & 15;

    for (int gs = blockIdx.x; gs < ngroups; gs += gridDim.x) {
        float4 hv;
        int loadnode = gs * 8 + (t >> 4);
        if (loadnode < n) hv = in4[gs * 128 + t];
        else hv = make_float4(0.f, 0.f, 0.f, 0.f);
        ((float4*)sH)[t] = hv;
        __syncthreads();

        float4 acc = sB4[g];
        const float* hrow = sH + nl * 64;
        #pragma unroll
        for (int k = 0; k < 64; k++) {
            float  hk = hrow[k];
            float4 w  = sW[k * 16 + g];
            acc.x = fmaf(hk, w.x, acc.x);
            acc.y = fmaf(hk, w.y, acc.y);
            acc.z = fmaf(hk, w.z, acc.z);
            acc.w = fmaf(hk, w.w, acc.w);
        }
        if (relu) {
            acc.x = fmaxf(acc.x, 0.f); acc.y = fmaxf(acc.y, 0.f);
            acc.z = fmaxf(acc.z, 0.f); acc.w = fmaxf(acc.w, 0.f);
        }
        int node = gs * 8 + nl;
        if (node < n) out4[node * 16 + g] = acc;
        __syncthreads();
    }
}

// batch is sorted: find graph start offsets by binary search (deterministic, no atomics)
__global__ void k_gstart(const int* __restrict__ batch, int n) {
    int g = threadIdx.x;
    if (g > NGRAPH) return;
    if (g == NGRAPH) { g_gstart[NGRAPH] = n; return; }
    int lo = 0, hi = n;
    while (lo < hi) {
        int mid = (lo + hi) >> 1;
        if (batch[mid] < g) lo = mid + 1; else hi = mid;
    }
    g_gstart[g] = lo;
}

// mean-pool: one block per graph, 4 node-streams x 64 dims
__global__ void k_pool(int n) {
    int gid = blockIdx.x;
    int s = g_gstart[gid], e = g_gstart[gid + 1];
    int t = threadIdx.x;            // 256
    int d = t & 63, str = t >> 6;
    float acc = 0.f;
    for (int nn = s + str; nn < e; nn += 4) acc += g_h[(long)nn * HDIM + d];
    __shared__ float red[256];
    red[t] = acc;
    __syncthreads();
    if (t < 64) {
        float tot = red[t] + red[t + 64] + red[t + 128] + red[t + 192];
        float cnt = (float)(e - s);
        g_pooled[gid * HDIM + t] = tot / fmaxf(cnt, 1.f);
    }
}

// z = [pooled, ge] @ Wl + bl ; log_softmax. One thread per graph.
__global__ void k_final(const float* __restrict__ ge, const float* __restrict__ Wl,
                        const float* __restrict__ bl, float* __restrict__ out) {
    __shared__ float sW[128 * NCLS];
    __shared__ float sb[NCLS];
    int t = threadIdx.x;           // 128
    for (int i = t; i < 128 * NCLS; i += 128) sW[i] = Wl[i];
    if (t < NCLS) sb[t] = bl[t];
    __syncthreads();
    int g = t;
    float z[NCLS];
    #pragma unroll
    for (int c = 0; c < NCLS; c++) z[c] = sb[c];
    for (int k = 0; k < 64; k++) {
        float p = g_pooled[g * HDIM + k];
        #pragma unroll
        for (int c = 0; c < NCLS; c++) z[c] = fmaf(p, sW[k * NCLS + c], z[c]);
    }
    for (int k = 0; k < 64; k++) {
        float p = ge[g * 64 + k];
        #pragma unroll
        for (int c = 0; c < NCLS; c++) z[c] = fmaf(p, sW[(64 + k) * NCLS + c], z[c]);
    }
    float m = z[0];
    #pragma unroll
    for (int c = 1; c < NCLS; c++) m = fmaxf(m, z[c]);
    float s = 0.f;
    #pragma unroll
    for (int c = 0; c < NCLS; c++) s += expf(z[c] - m);
    float l = m + logf(s);
    #pragma unroll
    for (int c = 0; c < NCLS; c++) out[g * NCLS + c] = z[c] - l;
}

// ---------------- launch ----------------
extern "C" void kernel_launch(void* const* d_in, const int* in_sizes, int n_in,
                              void* d_out, int out_size) {
    const float* x     = (const float*)d_in[0];
    const int*   ei    = (const int*)d_in[1];
    const int*   batch = (const int*)d_in[2];
    const float* ge    = (const float*)d_in[3];
    const float* W1    = (const float*)d_in[4];
    const float* b1    = (const float*)d_in[5];
    const float* W2    = (const float*)d_in[6];
    const float* b2    = (const float*)d_in[7];
    const float* W3    = (const float*)d_in[8];
    const float* b3    = (const float*)d_in[9];
    const float* Wl    = (const float*)d_in[10];
    const float* bl    = (const float*)d_in[11];
    float* out = (float*)d_out;

    int n = in_sizes[0] / 2;    // x is [N,2]
    int e = in_sizes[1] / 2;    // edge_index is [2,E]
    int nb = (n + 1023) / 1024;

    // CSR build
    k_zero   <<<(n + 255) / 256, 256>>>(n);
    k_count  <<<(e + 255) / 256, 256>>>(ei + e, e);
    k_dinv   <<<(n + 255) / 256, 256>>>(n);
    k_scanA  <<<nb, 1024>>>(n);
    k_scanB  <<<1, 32>>>(nb);
    k_scanC  <<<(n + 255) / 256, 256>>>(n);
    k_scatter<<<(e + 255) / 256, 256>>>(ei, e);

    int aggGrid  = (n + 7) / 8;                 // 8 warps/block of 256
    int gemmGrid = aggGrid < 1184 ? aggGrid : 1184;

    // layer 1: aggregate raw 2-wide x, then linear+relu  (writes g_h)
    k_agg2 <<<(n + 127) / 128, 128>>>(x, n);
    k_lin1 <<<(n * HDIM + 255) / 256, 256>>>(W1, b1, n);

    // layer 2: agg(g_h) -> g_a ; g_a @ W2 + b2 -> g_h (relu)
    k_agg64<<<aggGrid, 256>>>(0, 1, n);
    k_gemm <<<gemmGrid, 128>>>(1, 0, W2, b2, n, 1);

    // layer 3: agg(g_h) -> g_a ; g_a @ W3 + b3 -> g_h
    k_agg64<<<aggGrid, 256>>>(0, 1, n);
    k_gemm <<<gemmGrid, 128>>>(1, 0, W3, b3, n, 0);

    // mean pool + head
    k_gstart<<<1, 256>>>(batch, n);
    k_pool  <<<NGRAPH, 256>>>(n);
    k_final <<<1, 128>>>(ge, Wl, bl, out);
}

// round 3
// speedup vs baseline: 1.2710x; 1.2710x over previous
#include <cuda_runtime.h>
#include <math.h>

#define NMAX   100000
#define NSTR   100096     // node stride for transposed buffer (mult of 128)
#define EMAX   1000000
#define HDIM   64
#define NGRAPH 128
#define NCLS   5

typedef unsigned long long u64;

// ---------------- scratch (device globals; never passed from host) ----------------
__device__ int   g_deg[NMAX];
__device__ int   g_cursor[NMAX];
__device__ int   g_off[NMAX];
__device__ int   g_bsum[128];
__device__ float g_dinv[NMAX];
__device__ __align__(8)  int2  g_cedge[EMAX];          // {src, __float_as_int(norm)}
__device__ __align__(16) float g_ax[NMAX * 2];
__device__ __align__(16) float g_bufA[HDIM * NSTR];    // t2 transposed [c][node]; later h3 row-major
__device__ __align__(16) float g_bufB[NMAX * HDIM];    // g2 = relu(t2@W2+b2)@W3, row-major
__device__ __align__(16) float g_pooled[NGRAPH * HDIM];

// ---------------- f32x2 packed helpers ----------------
__device__ __forceinline__ u64 pack2(float a, float b) {
    u64 r; asm("mov.b64 %0, {%1, %2};" : "=l"(r) : "f"(a), "f"(b)); return r;
}
__device__ __forceinline__ void unpack2(u64 v, float& a, float& b) {
    asm("mov.b64 {%0, %1}, %2;" : "=f"(a), "=f"(b) : "l"(v));
}
__device__ __forceinline__ void fma2(u64& d, u64 a, u64 b, u64 c) {
    asm("fma.rn.f32x2 %0, %1, %2, %3;" : "=l"(d) : "l"(a), "l"(b), "l"(c));
}

// ---------------- CSR build ----------------
__global__ void k_zero(int n) {
    int i = blockIdx.x * blockDim.x + threadIdx.x;
    if (i < n) { g_deg[i] = 0; g_cursor[i] = 0; }
}

__global__ void k_count(const int* __restrict__ dst, int e) {
    int i = blockIdx.x * blockDim.x + threadIdx.x;
    if (i < e) atomicAdd(&g_deg[dst[i]], 1);
}

// per-block exclusive scan of deg -> off, block sums -> g_bsum; also dinv
__global__ void k_scanA(int n) {
    int i = blockIdx.x * 1024 + threadIdx.x;
    int v = (i < n) ? g_deg[i] : 0;
    if (i < n) g_dinv[i] = rsqrtf((float)(v + 1));       // +1 self-loop
    int lane = threadIdx.x & 31, wid = threadIdx.x >> 5;
    int x = v;
    #pragma unroll
    for (int o = 1; o < 32; o <<= 1) {
        int y = __shfl_up_sync(0xffffffffu, x, o);
        if (lane >= o) x += y;
    }
    __shared__ int ws[32];
    if (lane == 31) ws[wid] = x;
    __syncthreads();
    if (wid == 0) {
        int s = ws[lane];
        #pragma unroll
        for (int o = 1; o < 32; o <<= 1) {
            int y = __shfl_up_sync(0xffffffffu, s, o);
            if (lane >= o) s += y;
        }
        ws[lane] = s;
    }
    __syncthreads();
    int warpoff = (wid == 0) ? 0 : ws[wid - 1];
    if (i < n) g_off[i] = warpoff + x - v;
    if (threadIdx.x == 0) g_bsum[blockIdx.x] = ws[31];
}

// warp-parallel scan of block sums (was a serial dependent-load chain)
__global__ void k_scanB(int nb) {
    int lane = threadIdx.x;                  // 32 threads
    int per = (nb + 31) / 32;                // <= 4 for nb <= 128
    int s0 = lane * per;
    int vals[4]; int sum = 0;
    for (int k = 0; k < per; k++) {
        int idx = s0 + k;
        int v = (idx < nb) ? g_bsum[idx] : 0;
        vals[k] = sum; sum += v;
    }
    int x = sum;
    #pragma unroll
    for (int o = 1; o < 32; o <<= 1) {
        int y = __shfl_up_sync(0xffffffffu, x, o);
        if (lane >= o) x += y;
    }
    int excl = x - sum;
    for (int k = 0; k < per; k++) {
        int idx = s0 + k;
        if (idx < nb) g_bsum[idx] = excl + vals[k];
    }
}

__global__ void k_scanC(int n) {
    int i = blockIdx.x * blockDim.x + threadIdx.x;
    if (i < n) g_off[i] += g_bsum[i >> 10];
}

__global__ void k_scatter(const int* __restrict__ ei, int e) {
    int i = blockIdx.x * blockDim.x + threadIdx.x;
    if (i >= e) return;
    int s = ei[i];
    int d = ei[e + i];
    int p = g_off[d] + atomicAdd(&g_cursor[d], 1);
    int2 ed; ed.x = s; ed.y = __float_as_int(g_dinv[s] * g_dinv[d]);
    g_cedge[p] = ed;
}

// ---------------- layer 1: aggregate raw 2-wide x ----------------
__global__ void k_agg2(const float* __restrict__ x, int n) {
    int v = blockIdx.x * blockDim.x + threadIdx.x;
    if (v >= n) return;
    const float2* x2 = (const float2*)x;
    float ax = 0.f, ay = 0.f;
    int st = g_off[v], c = g_deg[v];
    for (int j = 0; j < c; j++) {
        int2 ed = __ldg(&g_cedge[st + j]);
        float nm = __int_as_float(ed.y);
        float2 xv = __ldg(&x2[ed.x]);
        ax = fmaf(nm, xv.x, ax);
        ay = fmaf(nm, xv.y, ay);
    }
    float dv = g_dinv[v], nm = dv * dv;
    float2 xv = __ldg(&x2[v]);
    ax = fmaf(nm, xv.x, ax);
    ay = fmaf(nm, xv.y, ay);
    g_ax[2 * v] = ax;
    g_ax[2 * v + 1] = ay;
}

// ---------------- layer 2 aggregation with lin1 fused (8B gathers, not 256B) ----
// t2[v] = sum_e norm * relu(W1^T ax[s] + b1)  + dinv^2 * relu(W1^T ax[v] + b1)
// output written TRANSPOSED [c][node] for k_mlp's coalesced tile loads
__global__ void k_l2agg(const float* __restrict__ W1, const float* __restrict__ b1, int n) {
    __shared__ float sT[64 * 9];
    int t = threadIdx.x, wid = t >> 5, lane = t & 31;
    int v = blockIdx.x * 8 + wid;
    float w1x0 = W1[lane],      w1y0 = W1[64 + lane],  bb0 = b1[lane];
    float w1x1 = W1[lane + 32], w1y1 = W1[96 + lane],  bb1 = b1[lane + 32];
    float a0 = 0.f, a1 = 0.f;
    if (v < n) {
        int st = g_off[v], c = g_deg[v];
        for (int j = 0; j < c; j++) {
            int2 ed = __ldg(&g_cedge[st + j]);
            float nm = __int_as_float(ed.y);
            float2 ax = *(const float2*)(g_ax + 2 * ed.x);
            float h0 = fmaxf(fmaf(ax.x, w1x0, fmaf(ax.y, w1y0, bb0)), 0.f);
            float h1 = fmaxf(fmaf(ax.x, w1x1, fmaf(ax.y, w1y1, bb1)), 0.f);
            a0 = fmaf(nm, h0, a0);
            a1 = fmaf(nm, h1, a1);
        }
        float dv = g_dinv[v], nm = dv * dv;
        float2 ax = *(const float2*)(g_ax + 2 * v);
        float h0 = fmaxf(fmaf(ax.x, w1x0, fmaf(ax.y, w1y0, bb0)), 0.f);
        float h1 = fmaxf(fmaf(ax.x, w1x1, fmaf(ax.y, w1y1, bb1)), 0.f);
        a0 = fmaf(nm, h0, a0);
        a1 = fmaf(nm, h1, a1);
    }
    sT[lane * 9 + wid] = a0;
    sT[(lane + 32) * 9 + wid] = a1;
    __syncthreads();
    int base = blockIdx.x * 8;
    for (int q = t; q < 512; q += 256) {
        int c = q >> 3, j = q & 7;
        if (base + j < n) g_bufA[(size_t)c * NSTR + base + j] = sT[c * 9 + j];
    }
}

// ---------------- fused MLP: g2 = relu(t2 @ W2 + b2) @ W3  (f32x2 packed FMA) ----
// 128-node tiles, 128 threads, thread tile = 8 nodes x 8 cols (4 f32x2 pairs)
__global__ __launch_bounds__(128, 2) void k_mlp(const float* __restrict__ W2,
                                                const float* __restrict__ b2,
                                                const float* __restrict__ W3,
                                                int n) {
    extern __shared__ float sm[];
    float* sW2 = sm;                 // 64*64
    float* sW3 = sm + 4096;          // 64*64
    float* sA  = sm + 8192;          // [64][132]  input tile  (k-major)
    float* sB  = sA + 64 * 132;      // [64][132]  intermediate (k-major)
    const int t  = threadIdx.x;
    const int cg = t & 7;            // col group: cols cg*8 .. cg*8+7
    const int ng = t >> 3;           // node group: nodes ng*8 .. ng*8+7

    for (int i = t; i < 1024; i += 128) {
        ((float4*)sW2)[i] = ((const float4*)W2)[i];
        ((float4*)sW3)[i] = ((const float4*)W3)[i];
    }
    u64 bias2[4];
    #pragma unroll
    for (int j = 0; j < 4; j++)
        bias2[j] = *(const u64*)(b2 + cg * 8 + 2 * j);
    __syncthreads();

    const int ntiles = (n + 127) >> 7;
    for (int tile = blockIdx.x; tile < ntiles; tile += gridDim.x) {
        const int base = tile << 7;
        // load input tile (transposed source, coalesced)
        for (int q = t; q < 64 * 32; q += 128) {
            int c = q >> 5, v4 = (q & 31) << 2;
            float4 val;
            if (base + v4 + 3 < n) {
                val = *(const float4*)(g_bufA + (size_t)c * NSTR + base + v4);
            } else {
                const float* p = g_bufA + (size_t)c * NSTR + base + v4;
                int rem = n - base - v4;
                val.x = (rem > 0) ? p[0] : 0.f;
                val.y = (rem > 1) ? p[1] : 0.f;
                val.z = (rem > 2) ? p[2] : 0.f;
                val.w = (rem > 3) ? p[3] : 0.f;
            }
            *(float4*)(sA + c * 132 + v4) = val;
        }
        __syncthreads();

        // GEMM1: acc = t2 @ W2 + b2
        u64 acc[8][4];
        #pragma unroll
        for (int i = 0; i < 8; i++)
            #pragma unroll
            for (int j = 0; j < 4; j++) acc[i][j] = bias2[j];
        #pragma unroll 8
        for (int k = 0; k < 64; k++) {
            float4 h0 = *(const float4*)(sA + k * 132 + ng * 8);
            float4 h1 = *(const float4*)(sA + k * 132 + ng * 8 + 4);
            u64 hh[8];
            hh[0] = pack2(h0.x, h0.x); hh[1] = pack2(h0.y, h0.y);
            hh[2] = pack2(h0.z, h0.z); hh[3] = pack2(h0.w, h0.w);
            hh[4] = pack2(h1.x, h1.x); hh[5] = pack2(h1.y, h1.y);
            hh[6] = pack2(h1.z, h1.z); hh[7] = pack2(h1.w, h1.w);
            #pragma unroll
            for (int j = 0; j < 4; j++) {
                u64 w = *(const u64*)(sW2 + k * 64 + cg * 8 + 2 * j);
                #pragma unroll
                for (int i = 0; i < 8; i++) fma2(acc[i][j], hh[i], w, acc[i][j]);
            }
        }
        // relu -> sB (k-major for GEMM2)
        #pragma unroll
        for (int j = 0; j < 4; j++) {
            float lo[8], hi[8];
            #pragma unroll
            for (int i = 0; i < 8; i++) {
                float a, b; unpack2(acc[i][j], a, b);
                lo[i] = fmaxf(a, 0.f); hi[i] = fmaxf(b, 0.f);
            }
            int c0 = cg * 8 + 2 * j, c1 = c0 + 1;
            *(float4*)(sB + c0 * 132 + ng * 8)     = make_float4(lo[0], lo[1], lo[2], lo[3]);
            *(float4*)(sB + c0 * 132 + ng * 8 + 4) = make_float4(lo[4], lo[5], lo[6], lo[7]);
            *(float4*)(sB + c1 * 132 + ng * 8)     = make_float4(hi[0], hi[1], hi[2], hi[3]);
            *(float4*)(sB + c1 * 132 + ng * 8 + 4) = make_float4(hi[4], hi[5], hi[6], hi[7]);
        }
        __syncthreads();

        // GEMM2: g2 = h2 @ W3 (no bias)
        u64 acc2[8][4];
        #pragma unroll
        for (int i = 0; i < 8; i++)
            #pragma unroll
            for (int j = 0; j < 4; j++) acc2[i][j] = 0ull;
        #pragma unroll 8
        for (int k = 0; k < 64; k++) {
            float4 h0 = *(const float4*)(sB + k * 132 + ng * 8);
            float4 h1 = *(const float4*)(sB + k * 132 + ng * 8 + 4);
            u64 hh[8];
            hh[0] = pack2(h0.x, h0.x); hh[1] = pack2(h0.y, h0.y);
            hh[2] = pack2(h0.z, h0.z); hh[3] = pack2(h0.w, h0.w);
            hh[4] = pack2(h1.x, h1.x); hh[5] = pack2(h1.y, h1.y);
            hh[6] = pack2(h1.z, h1.z); hh[7] = pack2(h1.w, h1.w);
            #pragma unroll
            for (int j = 0; j < 4; j++) {
                u64 w = *(const u64*)(sW3 + k * 64 + cg * 8 + 2 * j);
                #pragma unroll
                for (int i = 0; i < 8; i++) fma2(acc2[i][j], hh[i], w, acc2[i][j]);
            }
        }
        #pragma unroll
        for (int i = 0; i < 8; i++) {
            int node = base + ng * 8 + i;
            if (node < n) {
                u64* dst = (u64*)(g_bufB + (size_t)node * 64 + cg * 8);
                #pragma unroll
                for (int j = 0; j < 4; j++) dst[j] = acc2[i][j];
            }
        }
        __syncthreads();
    }
}

// ---------------- layer 3 aggregation: h3 = agg(g2) + b3 ----------------
// warp per node; 2 edges in flight (half-warps), 16 lanes x float4 per row
__global__ void k_agg64(const float* __restrict__ b3, int n) {
    int t = threadIdx.x;
    int w = (blockIdx.x * blockDim.x + t) >> 5;
    int lane = t & 31;
    int half = lane >> 4, l16 = lane & 15;
    if (w >= n) return;
    int st = g_off[w], c = g_deg[w];
    float4 a = make_float4(0.f, 0.f, 0.f, 0.f);
    for (int j = half; j < c; j += 2) {
        int2 ed = __ldg(&g_cedge[st + j]);
        float nm = __int_as_float(ed.y);
        float4 vv = *(const float4*)(g_bufB + (size_t)ed.x * 64 + l16 * 4);
        a.x = fmaf(nm, vv.x, a.x); a.y = fmaf(nm, vv.y, a.y);
        a.z = fmaf(nm, vv.z, a.z); a.w = fmaf(nm, vv.w, a.w);
    }
    if (half == 0) {
        float dv = g_dinv[w], nm = dv * dv;
        float4 vv = *(const float4*)(g_bufB + (size_t)w * 64 + l16 * 4);
        a.x = fmaf(nm, vv.x, a.x); a.y = fmaf(nm, vv.y, a.y);
        a.z = fmaf(nm, vv.z, a.z); a.w = fmaf(nm, vv.w, a.w);
    }
    a.x += __shfl_xor_sync(0xffffffffu, a.x, 16);
    a.y += __shfl_xor_sync(0xffffffffu, a.y, 16);
    a.z += __shfl_xor_sync(0xffffffffu, a.z, 16);
    a.w += __shfl_xor_sync(0xffffffffu, a.w, 16);
    if (half == 0) {
        float4 bb = *(const float4*)(b3 + l16 * 4);
        a.x += bb.x; a.y += bb.y; a.z += bb.z; a.w += bb.w;
        *(float4*)(g_bufA + (size_t)w * 64 + l16 * 4) = a;   // h3 row-major
    }
}

// ---------------- mean pool (inline sorted-batch binary search) ----------------
__global__ void k_pool(const int* __restrict__ batch, int n) {
    __shared__ int sb[2];
    int gid = blockIdx.x;
    int t = threadIdx.x;          // 256
    if (t < 2) {
        int target = gid + t;
        int lo = 0, hi = n;
        while (lo < hi) {
            int mid = (lo + hi) >> 1;
            if (batch[mid] < target) lo = mid + 1; else hi = mid;
        }
        sb[t] = lo;
    }
    __syncthreads();
    int s = sb[0], e = sb[1];
    int d = t & 63, str = t >> 6;
    float acc = 0.f;
    for (int nn = s + str; nn < e; nn += 4) acc += g_bufA[(size_t)nn * 64 + d];
    __shared__ float red[256];
    red[t] = acc;
    __syncthreads();
    if (t < 64) {
        float tot = red[t] + red[t + 64] + red[t + 128] + red[t + 192];
        g_pooled[gid * 64 + t] = tot / fmaxf((float)(e - s), 1.f);
    }
}

// ---------------- head: z = [pooled, ge] @ Wl + bl ; log_softmax ----------------
__global__ void k_final(const float* __restrict__ ge, const float* __restrict__ Wl,
                        const float* __restrict__ bl, float* __restrict__ out) {
    __shared__ float sW[128 * NCLS];
    __shared__ float sbv[NCLS];
    int t = threadIdx.x;          // 128
    for (int i = t; i < 128 * NCLS; i += 128) sW[i] = Wl[i];
    if (t < NCLS) sbv[t] = bl[t];
    __syncthreads();
    int g = t;
    float z[NCLS];
    #pragma unroll
    for (int c = 0; c < NCLS; c++) z[c] = sbv[c];
    for (int k = 0; k < 64; k++) {
        float p = g_pooled[g * HDIM + k];
        #pragma unroll
        for (int c = 0; c < NCLS; c++) z[c] = fmaf(p, sW[k * NCLS + c], z[c]);
    }
    for (int k = 0; k < 64; k++) {
        float p = ge[g * 64 + k];
        #pragma unroll
        for (int c = 0; c < NCLS; c++) z[c] = fmaf(p, sW[(64 + k) * NCLS + c], z[c]);
    }
    float m = z[0];
    #pragma unroll
    for (int c = 1; c < NCLS; c++) m = fmaxf(m, z[c]);
    float s = 0.f;
    #pragma unroll
    for (int c = 0; c < NCLS; c++) s += expf(z[c] - m);
    float l = m + logf(s);
    #pragma unroll
    for (int c = 0; c < NCLS; c++) out[g * NCLS + c] = z[c] - l;
}

// ---------------- launch ----------------
extern "C" void kernel_launch(void* const* d_in, const int* in_sizes, int n_in,
                              void* d_out, int out_size) {
    const float* x     = (const float*)d_in[0];
    const int*   ei    = (const int*)d_in[1];
    const int*   batch = (const int*)d_in[2];
    const float* ge    = (const float*)d_in[3];
    const float* W1    = (const float*)d_in[4];
    const float* b1    = (const float*)d_in[5];
    const float* W2    = (const float*)d_in[6];
    const float* b2    = (const float*)d_in[7];
    const float* W3    = (const float*)d_in[8];
    const float* b3    = (const float*)d_in[9];
    const float* Wl    = (const float*)d_in[10];
    const float* bl    = (const float*)d_in[11];
    float* out = (float*)d_out;

    int n  = in_sizes[0] / 2;      // x is [N,2]
    int e  = in_sizes[1] / 2;      // edge_index is [2,E]
    int nb = (n + 1023) / 1024;

    static const int mlp_smem = (4096 + 4096 + 64 * 132 * 2) * (int)sizeof(float);
    cudaFuncSetAttribute(k_mlp, cudaFuncAttributeMaxDynamicSharedMemorySize, mlp_smem);

    // CSR build
    k_zero   <<<(n + 255) / 256, 256>>>(n);
    k_count  <<<(e + 255) / 256, 256>>>(ei + e, e);
    k_scanA  <<<nb, 1024>>>(n);
    k_scanB  <<<1, 32>>>(nb);
    k_scanC  <<<(n + 255) / 256, 256>>>(n);
    k_scatter<<<(e + 255) / 256, 256>>>(ei, e);

    // layer 1 pre-aggregation (linear commutes)
    k_agg2 <<<(n + 127) / 128, 128>>>(x, n);

    // layer 2 aggregation with lin1 fused -> t2 (transposed)
    k_l2agg<<<(n + 7) / 8, 256>>>(W1, b1, n);

    // fused GEMM2 -> relu -> GEMM3
    k_mlp  <<<296, 128, mlp_smem>>>(W2, b2, W3, n);

    // layer 3 aggregation + b3 -> h3
    k_agg64<<<(n + 7) / 8, 256>>>(b3, n);

    // mean pool + head
    k_pool <<<NGRAPH, 256>>>(batch, n);
    k_final<<<1, 128>>>(ge, Wl, bl, out);
}

// round 4
// speedup vs baseline: 1.4416x; 1.1342x over previous
#include <cuda_runtime.h>
#include <cuda_bf16.h>
#include <math.h>

#define NMAX   100000
#define NSTR   100096     // node stride for transposed buffer (mult of 128)
#define EMAX   1000000
#define HDIM   64
#define NGRAPH 128
#define NCLS   5

typedef unsigned long long u64;

// ---------------- scratch (device globals; never passed from host) ----------------
__device__ int   g_deg[NMAX];
__device__ int   g_cursor[NMAX];
__device__ int   g_off[NMAX];
__device__ int   g_flag[128];
__device__ int   g_poolctr;
__device__ float g_dinv[NMAX];
__device__ __align__(8)  int2  g_cedge[EMAX];          // {src, __float_as_int(norm)}
__device__ __align__(16) float g_ax[NMAX * 2];
__device__ __align__(16) float g_bufA[HDIM * NSTR];    // t2 transposed [c][node]; later h3 row-major
__device__ __align__(16) __nv_bfloat16 g_bufBh[NMAX * HDIM]; // g2 in bf16, row-major
__device__ __align__(16) float g_pooled[NGRAPH * HDIM];

// ---------------- packed helpers ----------------
__device__ __forceinline__ u64 pack2(float a, float b) {
    u64 r; asm("mov.b64 %0, {%1, %2};" : "=l"(r) : "f"(a), "f"(b)); return r;
}
__device__ __forceinline__ void unpack2(u64 v, float& a, float& b) {
    asm("mov.b64 {%0, %1}, %2;" : "=f"(a), "=f"(b) : "l"(v));
}
__device__ __forceinline__ void fma2(u64& d, u64 a, u64 b, u64 c) {
    asm("fma.rn.f32x2 %0, %1, %2, %3;" : "=l"(d) : "l"(a), "l"(b), "l"(c));
}
// pack (lo, hi) -> bf16x2 with lo in the low 16 bits
__device__ __forceinline__ unsigned bf16pack(float lo, float hi) {
    unsigned r; asm("cvt.rn.bf16x2.f32 %0, %1, %2;" : "=r"(r) : "f"(hi), "f"(lo)); return r;
}

// ---------------- CSR build ----------------
__global__ void k_zero(int n) {
    int i = blockIdx.x * blockDim.x + threadIdx.x;
    if (i < n) { g_deg[i] = 0; g_cursor[i] = 0; }
    if (i < 128) g_flag[i] = 0;
}

__global__ void k_count(const int* __restrict__ dst, int e) {
    int i = blockIdx.x * blockDim.x + threadIdx.x;
    if (i < e) atomicAdd(&g_deg[dst[i]], 1);
}

// single-pass exclusive scan of deg -> off (decoupled lookback), also dinv.
// grid = ceil(n/1024) = 98 blocks, all resident simultaneously (148 SMs).
__global__ void k_scan(int n) {
    int b = blockIdx.x;
    int i = (b << 10) + threadIdx.x;
    int v = (i < n) ? g_deg[i] : 0;
    if (i < n) g_dinv[i] = rsqrtf((float)(v + 1));       // +1 self-loop
    int lane = threadIdx.x & 31, wid = threadIdx.x >> 5;
    int x = v;
    #pragma unroll
    for (int o = 1; o < 32; o <<= 1) {
        int y = __shfl_up_sync(0xffffffffu, x, o);
        if (lane >= o) x += y;
    }
    __shared__ int ws[32];
    __shared__ int s_prefix;
    if (lane == 31) ws[wid] = x;
    __syncthreads();
    if (wid == 0) {
        int s = ws[lane];
        #pragma unroll
        for (int o = 1; o < 32; o <<= 1) {
            int y = __shfl_up_sync(0xffffffffu, s, o);
            if (lane >= o) s += y;
        }
        ws[lane] = s;
    }
    __syncthreads();
    int warpoff = (wid == 0) ? 0 : ws[wid - 1];
    int total = ws[31];
    // publish this block's aggregate (MSB = published marker; total < 2^31)
    if (threadIdx.x == 0) atomicExch(&g_flag[b], (int)(0x80000000u | (unsigned)total));
    // warp 0: sum all predecessor aggregates (lookback)
    if (threadIdx.x < 32) {
        int sum = 0;
        for (int p = b - 1 - (int)threadIdx.x; p >= 0; p -= 32) {
            int f;
            do { f = atomicAdd(&g_flag[p], 0); } while (f >= 0);   // negative == published
            sum += f & 0x7fffffff;
        }
        #pragma unroll
        for (int o = 16; o; o >>= 1) sum += __shfl_xor_sync(0xffffffffu, sum, o);
        if (threadIdx.x == 0) s_prefix = sum;
    }
    __syncthreads();
    if (i < n) g_off[i] = s_prefix + warpoff + x - v;
}

__global__ void k_scatter(const int* __restrict__ ei, int e) {
    int i = blockIdx.x * blockDim.x + threadIdx.x;
    if (i >= e) return;
    int s = ei[i];
    int d = ei[e + i];
    int p = g_off[d] + atomicAdd(&g_cursor[d], 1);
    int2 ed; ed.x = s; ed.y = __float_as_int(g_dinv[s] * g_dinv[d]);
    g_cedge[p] = ed;
}

// ---------------- layer 1: aggregate raw 2-wide x (4 edges in flight) ----------
__global__ void k_agg2(const float* __restrict__ x, int n) {
    int v = blockIdx.x * blockDim.x + threadIdx.x;
    if (v >= n) return;
    const float2* x2 = (const float2*)x;
    float ax = 0.f, ay = 0.f;
    int st = g_off[v], c = g_deg[v];
    for (int j = 0; j < c; j += 4) {
        int rem = c - j;
        int2 e0 = __ldg(&g_cedge[st + j]);
        int2 e1 = (rem > 1) ? __ldg(&g_cedge[st + j + 1]) : make_int2(0, 0);
        int2 e2 = (rem > 2) ? __ldg(&g_cedge[st + j + 2]) : make_int2(0, 0);
        int2 e3 = (rem > 3) ? __ldg(&g_cedge[st + j + 3]) : make_int2(0, 0);
        float2 x0 = __ldg(&x2[e0.x]);
        float2 x1 = __ldg(&x2[e1.x]);
        float2 x2v = __ldg(&x2[e2.x]);
        float2 x3 = __ldg(&x2[e3.x]);
        float n0 = __int_as_float(e0.y), n1 = __int_as_float(e1.y);
        float n2 = __int_as_float(e2.y), n3 = __int_as_float(e3.y);
        ax = fmaf(n0, x0.x, ax); ay = fmaf(n0, x0.y, ay);
        ax = fmaf(n1, x1.x, ax); ay = fmaf(n1, x1.y, ay);
        ax = fmaf(n2, x2v.x, ax); ay = fmaf(n2, x2v.y, ay);
        ax = fmaf(n3, x3.x, ax); ay = fmaf(n3, x3.y, ay);
    }
    float dv = g_dinv[v], nm = dv * dv;
    float2 xv = __ldg(&x2[v]);
    ax = fmaf(nm, xv.x, ax);
    ay = fmaf(nm, xv.y, ay);
    g_ax[2 * v] = ax;
    g_ax[2 * v + 1] = ay;
}

// ---------------- layer 2 aggregation with lin1 fused (4 edges in flight) -------
// t2[v] = sum_e norm * relu(W1^T ax[s] + b1) + dinv^2 * relu(W1^T ax[v] + b1)
// output written TRANSPOSED [c][node]
__global__ void k_l2agg(const float* __restrict__ W1, const float* __restrict__ b1, int n) {
    __shared__ float sT[64 * 9];
    int t = threadIdx.x, wid = t >> 5, lane = t & 31;
    int v = blockIdx.x * 8 + wid;
    float w1x0 = W1[lane],      w1y0 = W1[64 + lane],  bb0 = b1[lane];
    float w1x1 = W1[lane + 32], w1y1 = W1[96 + lane],  bb1 = b1[lane + 32];
    float a0 = 0.f, a1 = 0.f;
    if (v < n) {
        int st = g_off[v], c = g_deg[v];
        for (int j = 0; j < c; j += 4) {
            int rem = c - j;
            int2 e0 = __ldg(&g_cedge[st + j]);
            int2 e1 = (rem > 1) ? __ldg(&g_cedge[st + j + 1]) : make_int2(0, 0);
            int2 e2 = (rem > 2) ? __ldg(&g_cedge[st + j + 2]) : make_int2(0, 0);
            int2 e3 = (rem > 3) ? __ldg(&g_cedge[st + j + 3]) : make_int2(0, 0);
            float2 q0 = *(const float2*)(g_ax + 2 * e0.x);
            float2 q1 = *(const float2*)(g_ax + 2 * e1.x);
            float2 q2 = *(const float2*)(g_ax + 2 * e2.x);
            float2 q3 = *(const float2*)(g_ax + 2 * e3.x);
            float n0 = __int_as_float(e0.y), n1 = __int_as_float(e1.y);
            float n2 = __int_as_float(e2.y), n3 = __int_as_float(e3.y);
            float h;
            h = fmaxf(fmaf(q0.x, w1x0, fmaf(q0.y, w1y0, bb0)), 0.f); a0 = fmaf(n0, h, a0);
            h = fmaxf(fmaf(q0.x, w1x1, fmaf(q0.y, w1y1, bb1)), 0.f); a1 = fmaf(n0, h, a1);
            h = fmaxf(fmaf(q1.x, w1x0, fmaf(q1.y, w1y0, bb0)), 0.f); a0 = fmaf(n1, h, a0);
            h = fmaxf(fmaf(q1.x, w1x1, fmaf(q1.y, w1y1, bb1)), 0.f); a1 = fmaf(n1, h, a1);
            h = fmaxf(fmaf(q2.x, w1x0, fmaf(q2.y, w1y0, bb0)), 0.f); a0 = fmaf(n2, h, a0);
            h = fmaxf(fmaf(q2.x, w1x1, fmaf(q2.y, w1y1, bb1)), 0.f); a1 = fmaf(n2, h, a1);
            h = fmaxf(fmaf(q3.x, w1x0, fmaf(q3.y, w1y0, bb0)), 0.f); a0 = fmaf(n3, h, a0);
            h = fmaxf(fmaf(q3.x, w1x1, fmaf(q3.y, w1y1, bb1)), 0.f); a1 = fmaf(n3, h, a1);
        }
        float dv = g_dinv[v], nm = dv * dv;
        float2 q = *(const float2*)(g_ax + 2 * v);
        float h;
        h = fmaxf(fmaf(q.x, w1x0, fmaf(q.y, w1y0, bb0)), 0.f); a0 = fmaf(nm, h, a0);
        h = fmaxf(fmaf(q.x, w1x1, fmaf(q.y, w1y1, bb1)), 0.f); a1 = fmaf(nm, h, a1);
    }
    sT[lane * 9 + wid] = a0;
    sT[(lane + 32) * 9 + wid] = a1;
    __syncthreads();
    int base = blockIdx.x * 8;
    for (int q = t; q < 512; q += 256) {
        int c = q >> 3, j = q & 7;
        if (base + j < n) g_bufA[(size_t)c * NSTR + base + j] = sT[c * 9 + j];
    }
}

// ---------------- fused MLP: g2 = relu(t2 @ W2 + b2) @ W3 -> bf16 ----------------
__global__ __launch_bounds__(128, 2) void k_mlp(const float* __restrict__ W2,
                                                const float* __restrict__ b2,
                                                const float* __restrict__ W3,
                                                int n) {
    extern __shared__ float sm[];
    float* sW2 = sm;                 // 64*64
    float* sW3 = sm + 4096;          // 64*64
    float* sA  = sm + 8192;          // [64][132]
    float* sB  = sA + 64 * 132;      // [64][132]
    const int t  = threadIdx.x;
    const int cg = t & 7;
    const int ng = t >> 3;

    for (int i = t; i < 1024; i += 128) {
        ((float4*)sW2)[i] = ((const float4*)W2)[i];
        ((float4*)sW3)[i] = ((const float4*)W3)[i];
    }
    u64 bias2[4];
    #pragma unroll
    for (int j = 0; j < 4; j++)
        bias2[j] = *(const u64*)(b2 + cg * 8 + 2 * j);
    __syncthreads();

    const int ntiles = (n + 127) >> 7;
    for (int tile = blockIdx.x; tile < ntiles; tile += gridDim.x) {
        const int base = tile << 7;
        for (int q = t; q < 64 * 32; q += 128) {
            int c = q >> 5, v4 = (q & 31) << 2;
            float4 val;
            if (base + v4 + 3 < n) {
                val = *(const float4*)(g_bufA + (size_t)c * NSTR + base + v4);
            } else {
                const float* p = g_bufA + (size_t)c * NSTR + base + v4;
                int rem = n - base - v4;
                val.x = (rem > 0) ? p[0] : 0.f;
                val.y = (rem > 1) ? p[1] : 0.f;
                val.z = (rem > 2) ? p[2] : 0.f;
                val.w = (rem > 3) ? p[3] : 0.f;
            }
            *(float4*)(sA + c * 132 + v4) = val;
        }
        __syncthreads();

        // GEMM1: acc = t2 @ W2 + b2
        u64 acc[8][4];
        #pragma unroll
        for (int i = 0; i < 8; i++)
            #pragma unroll
            for (int j = 0; j < 4; j++) acc[i][j] = bias2[j];
        #pragma unroll 8
        for (int k = 0; k < 64; k++) {
            float4 h0 = *(const float4*)(sA + k * 132 + ng * 8);
            float4 h1 = *(const float4*)(sA + k * 132 + ng * 8 + 4);
            u64 hh[8];
            hh[0] = pack2(h0.x, h0.x); hh[1] = pack2(h0.y, h0.y);
            hh[2] = pack2(h0.z, h0.z); hh[3] = pack2(h0.w, h0.w);
            hh[4] = pack2(h1.x, h1.x); hh[5] = pack2(h1.y, h1.y);
            hh[6] = pack2(h1.z, h1.z); hh[7] = pack2(h1.w, h1.w);
            #pragma unroll
            for (int j = 0; j < 4; j++) {
                u64 w = *(const u64*)(sW2 + k * 64 + cg * 8 + 2 * j);
                #pragma unroll
                for (int i = 0; i < 8; i++) fma2(acc[i][j], hh[i], w, acc[i][j]);
            }
        }
        // relu -> sB (k-major)
        #pragma unroll
        for (int j = 0; j < 4; j++) {
            float lo[8], hi[8];
            #pragma unroll
            for (int i = 0; i < 8; i++) {
                float a, b; unpack2(acc[i][j], a, b);
                lo[i] = fmaxf(a, 0.f); hi[i] = fmaxf(b, 0.f);
            }
            int c0 = cg * 8 + 2 * j, c1 = c0 + 1;
            *(float4*)(sB + c0 * 132 + ng * 8)     = make_float4(lo[0], lo[1], lo[2], lo[3]);
            *(float4*)(sB + c0 * 132 + ng * 8 + 4) = make_float4(lo[4], lo[5], lo[6], lo[7]);
            *(float4*)(sB + c1 * 132 + ng * 8)     = make_float4(hi[0], hi[1], hi[2], hi[3]);
            *(float4*)(sB + c1 * 132 + ng * 8 + 4) = make_float4(hi[4], hi[5], hi[6], hi[7]);
        }
        __syncthreads();

        // GEMM2: g2 = h2 @ W3 (no bias) -> bf16 rows
        u64 acc2[8][4];
        #pragma unroll
        for (int i = 0; i < 8; i++)
            #pragma unroll
            for (int j = 0; j < 4; j++) acc2[i][j] = 0ull;
        #pragma unroll 8
        for (int k = 0; k < 64; k++) {
            float4 h0 = *(const float4*)(sB + k * 132 + ng * 8);
            float4 h1 = *(const float4*)(sB + k * 132 + ng * 8 + 4);
            u64 hh[8];
            hh[0] = pack2(h0.x, h0.x); hh[1] = pack2(h0.y, h0.y);
            hh[2] = pack2(h0.z, h0.z); hh[3] = pack2(h0.w, h0.w);
            hh[4] = pack2(h1.x, h1.x); hh[5] = pack2(h1.y, h1.y);
            hh[6] = pack2(h1.z, h1.z); hh[7] = pack2(h1.w, h1.w);
            #pragma unroll
            for (int j = 0; j < 4; j++) {
                u64 w = *(const u64*)(sW3 + k * 64 + cg * 8 + 2 * j);
                #pragma unroll
                for (int i = 0; i < 8; i++) fma2(acc2[i][j], hh[i], w, acc2[i][j]);
            }
        }
        #pragma unroll
        for (int i = 0; i < 8; i++) {
            int node = base + ng * 8 + i;
            if (node < n) {
                unsigned r[4];
                #pragma unroll
                for (int j = 0; j < 4; j++) {
                    float a, b; unpack2(acc2[i][j], a, b);
                    r[j] = bf16pack(a, b);
                }
                *(uint4*)(g_bufBh + (size_t)node * 64 + cg * 8) = make_uint4(r[0], r[1], r[2], r[3]);
            }
        }
        __syncthreads();
    }
}

// ---------------- layer 3 aggregation: h3 = agg(g2_bf16) + b3 ----------------
// warp per node; 2 edges in flight (half-warps), 16 lanes x 4 bf16 per row
__global__ void k_agg64(const float* __restrict__ b3, int n) {
    int t = threadIdx.x;
    int w = (blockIdx.x * blockDim.x + t) >> 5;
    int lane = t & 31;
    int half = lane >> 4, l16 = lane & 15;
    if (w >= n) return;
    int st = g_off[w], c = g_deg[w];
    float4 a = make_float4(0.f, 0.f, 0.f, 0.f);
    int j = half;
    int2 ed = (j < c) ? __ldg(&g_cedge[st + j]) : make_int2(0, 0);
    while (j < c) {
        int jn = j + 2;
        int2 edn = (jn < c) ? __ldg(&g_cedge[st + jn]) : make_int2(0, 0);
        float nm = __int_as_float(ed.y);
        uint2 u = *(const uint2*)(g_bufBh + (size_t)ed.x * 64 + l16 * 4);
        float2 f01 = __bfloat1622float2(*(__nv_bfloat162*)&u.x);
        float2 f23 = __bfloat1622float2(*(__nv_bfloat162*)&u.y);
        a.x = fmaf(nm, f01.x, a.x); a.y = fmaf(nm, f01.y, a.y);
        a.z = fmaf(nm, f23.x, a.z); a.w = fmaf(nm, f23.y, a.w);
        ed = edn; j = jn;
    }
    if (half == 0) {
        float dv = g_dinv[w], nm = dv * dv;
        uint2 u = *(const uint2*)(g_bufBh + (size_t)w * 64 + l16 * 4);
        float2 f01 = __bfloat1622float2(*(__nv_bfloat162*)&u.x);
        float2 f23 = __bfloat1622float2(*(__nv_bfloat162*)&u.y);
        a.x = fmaf(nm, f01.x, a.x); a.y = fmaf(nm, f01.y, a.y);
        a.z = fmaf(nm, f23.x, a.z); a.w = fmaf(nm, f23.y, a.w);
    }
    a.x += __shfl_xor_sync(0xffffffffu, a.x, 16);
    a.y += __shfl_xor_sync(0xffffffffu, a.y, 16);
    a.z += __shfl_xor_sync(0xffffffffu, a.z, 16);
    a.w += __shfl_xor_sync(0xffffffffu, a.w, 16);
    if (half == 0) {
        float4 bb = *(const float4*)(b3 + l16 * 4);
        a.x += bb.x; a.y += bb.y; a.z += bb.z; a.w += bb.w;
        *(float4*)(g_bufA + (size_t)w * 64 + l16 * 4) = a;   // h3 row-major
    }
}

// ---------------- mean pool + head (last block runs the head) ----------------
__global__ void k_poolfinal(const int* __restrict__ batch, const float* __restrict__ ge,
                            const float* __restrict__ Wl, const float* __restrict__ bl,
                            float* __restrict__ out, int n) {
    __shared__ int sb[2];
    __shared__ float red[256];
    __shared__ int s_last;
    int gid = blockIdx.x;
    int t = threadIdx.x;          // 256
    if (t < 2) {
        int target = gid + t;
        int lo = 0, hi = n;
        while (lo < hi) {
            int mid = (lo + hi) >> 1;
            if (batch[mid] < target) lo = mid + 1; else hi = mid;
        }
        sb[t] = lo;
    }
    __syncthreads();
    int s = sb[0], e = sb[1];
    int d = t & 63, str = t >> 6;
    float acc = 0.f;
    for (int nn = s + str; nn < e; nn += 4) acc += g_bufA[(size_t)nn * 64 + d];
    red[t] = acc;
    __syncthreads();
    if (t < 64) {
        float tot = red[t] + red[t + 64] + red[t + 128] + red[t + 192];
        g_pooled[gid * 64 + t] = tot / fmaxf((float)(e - s), 1.f);
    }
    __threadfence();
    if (t == 0) s_last = (atomicAdd(&g_poolctr, 1) == NGRAPH - 1);
    __syncthreads();
    if (!s_last) return;

    // ---- head (runs once, in the last-finishing block) ----
    if (t == 0) g_poolctr = 0;    // reset for next replay
    __shared__ float sW[128 * NCLS];
    __shared__ float sbv[NCLS];
    for (int i = t; i < 128 * NCLS; i += 256) sW[i] = Wl[i];
    if (t < NCLS) sbv[t] = bl[t];
    __syncthreads();
    if (t < 128) {
        int g = t;
        float z[NCLS];
        #pragma unroll
        for (int c = 0; c < NCLS; c++) z[c] = sbv[c];
        for (int k = 0; k < 64; k++) {
            float p = g_pooled[g * HDIM + k];
            #pragma unroll
            for (int c = 0; c < NCLS; c++) z[c] = fmaf(p, sW[k * NCLS + c], z[c]);
        }
        for (int k = 0; k < 64; k++) {
            float p = ge[g * 64 + k];
            #pragma unroll
            for (int c = 0; c < NCLS; c++) z[c] = fmaf(p, sW[(64 + k) * NCLS + c], z[c]);
        }
        float m = z[0];
        #pragma unroll
        for (int c = 1; c < NCLS; c++) m = fmaxf(m, z[c]);
        float sum = 0.f;
        #pragma unroll
        for (int c = 0; c < NCLS; c++) sum += expf(z[c] - m);
        float l = m + logf(sum);
        #pragma unroll
        for (int c = 0; c < NCLS; c++) out[g * NCLS + c] = z[c] - l;
    }
}

// ---------------- launch ----------------
extern "C" void kernel_launch(void* const* d_in, const int* in_sizes, int n_in,
                              void* d_out, int out_size) {
    const float* x     = (const float*)d_in[0];
    const int*   ei    = (const int*)d_in[1];
    const int*   batch = (const int*)d_in[2];
    const float* ge    = (const float*)d_in[3];
    const float* W1    = (const float*)d_in[4];
    const float* b1    = (const float*)d_in[5];
    const float* W2    = (const float*)d_in[6];
    const float* b2    = (const float*)d_in[7];
    const float* W3    = (const float*)d_in[8];
    const float* b3    = (const float*)d_in[9];
    const float* Wl    = (const float*)d_in[10];
    const float* bl    = (const float*)d_in[11];
    float* out = (float*)d_out;

    int n  = in_sizes[0] / 2;      // x is [N,2]
    int e  = in_sizes[1] / 2;      // edge_index is [2,E]
    int nb = (n + 1023) / 1024;

    static const int mlp_smem = (4096 + 4096 + 64 * 132 * 2) * (int)sizeof(float);
    cudaFuncSetAttribute(k_mlp, cudaFuncAttributeMaxDynamicSharedMemorySize, mlp_smem);

    k_zero   <<<(n + 255) / 256, 256>>>(n);           // 0
    k_count  <<<(e + 255) / 256, 256>>>(ei + e, e);   // 1
    k_scan   <<<nb, 1024>>>(n);                       // 2  (lookback scan + dinv)
    k_scatter<<<(e + 255) / 256, 256>>>(ei, e);       // 3  <- profiled slot
    k_agg2   <<<(n + 127) / 128, 128>>>(x, n);        // 4
    k_l2agg  <<<(n + 7) / 8, 256>>>(W1, b1, n);       // 5
    k_mlp    <<<296, 128, mlp_smem>>>(W2, b2, W3, n); // 6
    k_agg64  <<<(n + 7) / 8, 256>>>(b3, n);           // 7
    k_poolfinal<<<NGRAPH, 256>>>(batch, ge, Wl, bl, out, n); // 8
}